// round 14
// baseline (speedup 1.0000x reference)
#include <cuda_runtime.h>
#include <cuda_fp16.h>

// CustomAttention: out[b,n] = b0 * sum_m tanh(a0*x[b,n]*x[b,m]) * x[b,m]
// B=16, N=4096. Symmetric 256x256 tiling at the MUFU result roofline.
// R14: asymmetric fusion. Off-diagonal blocks pay ~2 instructions
// (1 release-atomic per counter); only the 16 diagonal blocks per batch
// (scheduled LAST) spin on their tile's counter, then reduce + write out.
// Deletes the 5us reduce-kernel launch/ramp; avoids R9-R12's per-block
// epilogue tax. Deadlock-free: feeders never wait; 256 spinners << slots.

#define NBATCH 16
#define NDIM   4096
#define TILE   256
#define NTILE  (NDIM / TILE)              // 16
#define NOFF   (NTILE * (NTILE - 1) / 2)  // 120
#define NPAIR  (NOFF + NTILE)             // 136
#define BT     256

__device__ __half g_scratch[NBATCH][NTILE][NDIM];   // 2 MB, exclusive-write
__device__ int    g_arrive[NBATCH][NTILE];          // zero-init; self-resetting

__device__ __forceinline__ __half2 tanh2(__half2 v) {
    unsigned u = *reinterpret_cast<unsigned*>(&v);
    unsigned r;
    asm("tanh.approx.f16x2 %0, %1;" : "=r"(r) : "r"(u));
    return *reinterpret_cast<__half2*>(&r);
}
__device__ __forceinline__ unsigned h2u(__half2 v) { return *reinterpret_cast<unsigned*>(&v); }
__device__ __forceinline__ __half2 u2h(unsigned v) { return *reinterpret_cast<__half2*>(&v); }

__device__ __forceinline__ void arrive_release(int* ctr) {
    int old;
    asm volatile("atom.add.release.gpu.global.s32 %0, [%1], 1;"
                 : "=r"(old) : "l"(ctr) : "memory");
}
__device__ __forceinline__ int load_acquire(int* ctr) {
    int v;
    asm volatile("ld.acquire.gpu.global.s32 %0, [%1];"
                 : "=r"(v) : "l"(ctr) : "memory");
    return v;
}

__global__ __launch_bounds__(BT, 8)
void sym_tile_kernel(const float* __restrict__ x,
                     const float* __restrict__ a,
                     const float* __restrict__ bco,
                     float* __restrict__ out)
{
    __shared__ __half2 xhJd[4][64];            // replicated col tile, 2 KB
    __shared__ float2  colred[8][TILE / 2];    // 8 KB

    const int batch = blockIdx.y;
    const int tid   = threadIdx.x;
    const int w     = tid >> 5;
    const int L     = tid & 31;

    // bid 0..119: off-diagonal pairs I<J; bid 120..135: diagonal (LAST)
    int I, J;
    if (blockIdx.x < NOFF) {
        int q = blockIdx.x, i = 0;
        while (true) { int cnt = NTILE - 1 - i; if (q < cnt) break; q -= cnt; i++; }
        I = i; J = i + 1 + q;
    } else {
        I = J = blockIdx.x - NOFF;
    }

    const float* __restrict__ xb = x + batch * NDIM;

    // Fill replicated col tile: 4 rb x 64 entries
    {
        const int rb = tid >> 6;
        const int j  = tid & 63;
        const int pr = rb * 32 + (j & 31);
        float2 v = reinterpret_cast<const float2*>(xb + J * TILE)[pr];
        xhJd[rb][j] = __floats2half2_rn(v.x, v.y);
    }

    const float xn = xb[I * TILE + tid];
    const __half2 ch  = __float2half2_rn(a[0] * xn);
    const __half2 xi2 = __float2half2_rn(xn);
    __syncthreads();

    float row_f = 0.f;

    if (I == J) {
        // ---- diagonal block: compute, arrive, spin, reduce tile I ----
        #pragma unroll 1
        for (int rb = 0; rb < 4; ++rb) {
            __half2 racc = __float2half2_rn(0.f);
            #pragma unroll
            for (int k = 0; k < 32; ++k) {
                __half2 h = xhJd[rb][k];
                racc = __hfma2(tanh2(__hmul2(ch, h)), h, racc);
            }
            float2 f = __half22float2(racc);
            row_f += f.x + f.y;
        }
        g_scratch[batch][I][I * TILE + tid] = __float2half(row_f);
        __syncthreads();                       // all diag stores issued

        if (tid == 0) {
            arrive_release(&g_arrive[batch][I]);            // 16th may be us
            while (load_acquire(&g_arrive[batch][I]) < NTILE)
                __nanosleep(64);                            // off-diag tail
        }
        __syncthreads();                       // acquire observed -> whole block

        const int n = I * TILE + tid;          // coalesced: consecutive tid -> n
        float s0 = 0.f, s1 = 0.f;
        #pragma unroll
        for (int slot = 0; slot < NTILE / 2; ++slot) {
            s0 += __half2float(__ldcg(&g_scratch[batch][2 * slot][n]));
            s1 += __half2float(__ldcg(&g_scratch[batch][2 * slot + 1][n]));
        }
        out[batch * NDIM + n] = bco[0] * (s0 + s1);

        if (tid == 0)                          // reset for next graph replay
            g_arrive[batch][I] = 0;
    } else {
        // ---- off-diagonal block: compute, store, 2 atomics. done. ----
        #pragma unroll 1
        for (int rb = 0; rb < 4; ++rb) {
            __half2 racc = __float2half2_rn(0.f);
            __half2 cacc = __float2half2_rn(0.f);
            #pragma unroll
            for (int k = 0; k < 32; ++k) {
                __half2 h = xhJd[rb][L + k];             // affine LDS
                __half2 t = tanh2(__hmul2(ch, h));
                racc = __hfma2(t, h, racc);              // rows of I
                unsigned v2 = h2u(__hmul2(t, xi2));      // t*x_row -> rows of J
                unsigned rv = __shfl_sync(0xffffffffu, v2, L + 32 - k);
                cacc = __hadd2(cacc, u2h(rv));
            }
            float2 f = __half22float2(racc);
            row_f += f.x + f.y;
            colred[w][rb * 32 + L] = __half22float2(cacc);
        }
        __syncthreads();

        float s = 0.f;
        #pragma unroll
        for (int w2 = 0; w2 < 8; ++w2) {
            float2 f = colred[w2][tid >> 1];
            s += (tid & 1) ? f.y : f.x;
        }
        g_scratch[batch][J][I * TILE + tid] = __float2half(row_f); // rows I, slot J
        g_scratch[batch][I][J * TILE + tid] = __float2half(s);     // rows J, slot I

        __syncthreads();                       // all stores issued before arrival
        if (tid == 0)
            arrive_release(&g_arrive[batch][I]);
        else if (tid == 32)
            arrive_release(&g_arrive[batch][J]);
    }
}

extern "C" void kernel_launch(void* const* d_in, const int* in_sizes, int n_in,
                              void* d_out, int out_size)
{
    const float* x = (const float*)d_in[0];
    const float* a = (const float*)d_in[1];
    const float* b = (const float*)d_in[2];
    float* out = (float*)d_out;

    dim3 grid(NPAIR, NBATCH);               // 136 x 16 = 2176 blocks
    sym_tile_kernel<<<grid, BT>>>(x, a, b, out);
}

// round 15
// speedup vs baseline: 1.0070x; 1.0070x over previous
#include <cuda_runtime.h>
#include <cuda_fp16.h>

// CustomAttention: out[b,n] = b0 * sum_m tanh(a0*x[b,n]*x[b,m]) * x[b,m]
// B=16, N=4096. Symmetric 256x256 tiling at the MUFU f16x2 roofline (rt16).
// R15: fixed-point INT accumulation. Integer adds are exactly associative
// -> RED.ADD in any order is bit-deterministic. Each block REDs its
// partial (x 2^16) into one int32 per output; the 16th arriver per tile
// (acq_rel election) finalizes with ONE __ldcg per output. Kills the
// 16-deep/2MB reduce chains that stayed exposed in R6/R13/R14 (~5us).

#define NBATCH 16
#define NDIM   4096
#define TILE   256
#define NTILE  (NDIM / TILE)              // 16
#define NOFF   (NTILE * (NTILE - 1) / 2)  // 120
#define NPAIR  (NOFF + NTILE)             // 136
#define BT     256
#define FSCALE 65536.0f                   // 2^16 fixed point
#define INV_FSCALE (1.0f / 65536.0f)

__device__ int g_accum[NBATCH][NDIM];     // 256 KB, zero-init, self-resetting
__device__ int g_arrive[NBATCH][NTILE];   // zero-init, self-resetting

__device__ __forceinline__ __half2 tanh2(__half2 v) {
    unsigned u = *reinterpret_cast<unsigned*>(&v);
    unsigned r;
    asm("tanh.approx.f16x2 %0, %1;" : "=r"(r) : "r"(u));
    return *reinterpret_cast<__half2*>(&r);
}
__device__ __forceinline__ unsigned h2u(__half2 v) { return *reinterpret_cast<unsigned*>(&v); }
__device__ __forceinline__ __half2 u2h(unsigned v) { return *reinterpret_cast<__half2*>(&v); }

// Counter arrival with acq_rel: release our prior writes, acquire others'.
__device__ __forceinline__ int arrive_acqrel(int* ctr) {
    int old;
    asm volatile("atom.add.acq_rel.gpu.global.s32 %0, [%1], 1;"
                 : "=r"(old) : "l"(ctr) : "memory");
    return old;
}

// Finalize output tile R: one int load per output, scale, write, reset.
__device__ __forceinline__ void finalize_tile(int batch, int R, float b0,
                                              float* __restrict__ out, int tid)
{
    const int n = R * TILE + tid;
    int v = __ldcg(&g_accum[batch][n]);
    out[batch * NDIM + n] = b0 * ((float)v * INV_FSCALE);
    g_accum[batch][n] = 0;                 // reset for next graph replay
}

__global__ __launch_bounds__(BT, 8)
void sym_tile_kernel(const float* __restrict__ x,
                     const float* __restrict__ a,
                     const float* __restrict__ bco,
                     float* __restrict__ out)
{
    __shared__ __half2 xhJd[4][64];            // replicated col tile, 2 KB
    __shared__ float2  colred[8][TILE / 2];    // 8 KB
    __shared__ int     s_old[2];               // election results

    const int batch = blockIdx.y;
    const int tid   = threadIdx.x;
    const int w     = tid >> 5;
    const int L     = tid & 31;

    // bid 0..119: off-diagonal pairs I<J; bid 120..135: diagonal (LAST)
    int I, J;
    if (blockIdx.x < NOFF) {
        int q = blockIdx.x, i = 0;
        while (true) { int cnt = NTILE - 1 - i; if (q < cnt) break; q -= cnt; i++; }
        I = i; J = i + 1 + q;
    } else {
        I = J = blockIdx.x - NOFF;
    }

    const float* __restrict__ xb = x + batch * NDIM;

    // Fill replicated col tile: 4 rb x 64 entries
    {
        const int rb = tid >> 6;
        const int j  = tid & 63;
        const int pr = rb * 32 + (j & 31);
        float2 v = reinterpret_cast<const float2*>(xb + J * TILE)[pr];
        xhJd[rb][j] = __floats2half2_rn(v.x, v.y);
    }

    const float xn = xb[I * TILE + tid];
    const __half2 ch  = __float2half2_rn(a[0] * xn);
    const __half2 xi2 = __float2half2_rn(xn);
    __syncthreads();

    float row_f = 0.f;

    if (I == J) {
        #pragma unroll 1
        for (int rb = 0; rb < 4; ++rb) {
            __half2 racc = __float2half2_rn(0.f);
            #pragma unroll
            for (int k = 0; k < 32; ++k) {
                __half2 h = xhJd[rb][k];
                racc = __hfma2(tanh2(__hmul2(ch, h)), h, racc);
            }
            float2 f = __half22float2(racc);
            row_f += f.x + f.y;
        }
        // RED fixed-point partial into rows of I (spread, no return)
        atomicAdd(&g_accum[batch][I * TILE + tid], __float2int_rn(row_f * FSCALE));

        __syncthreads();                       // REDs issued before arrival
        if (tid == 0)
            s_old[0] = arrive_acqrel(&g_arrive[batch][I]);
        if (tid == 32)
            s_old[1] = -1;
    } else {
        #pragma unroll 1
        for (int rb = 0; rb < 4; ++rb) {
            __half2 racc = __float2half2_rn(0.f);
            __half2 cacc = __float2half2_rn(0.f);
            #pragma unroll
            for (int k = 0; k < 32; ++k) {
                __half2 h = xhJd[rb][L + k];             // affine LDS
                __half2 t = tanh2(__hmul2(ch, h));
                racc = __hfma2(t, h, racc);              // rows of I
                unsigned v2 = h2u(__hmul2(t, xi2));      // t*x_row -> rows of J
                unsigned rv = __shfl_sync(0xffffffffu, v2, L + 32 - k);
                cacc = __hadd2(cacc, u2h(rv));
            }
            float2 f = __half22float2(racc);
            row_f += f.x + f.y;
            colred[w][rb * 32 + L] = __half22float2(cacc);
        }
        __syncthreads();

        float s = 0.f;
        #pragma unroll
        for (int w2 = 0; w2 < 8; ++w2) {
            float2 f = colred[w2][tid >> 1];
            s += (tid & 1) ? f.y : f.x;
        }
        // RED fixed-point partials: rows of I (row side), rows of J (col side)
        atomicAdd(&g_accum[batch][I * TILE + tid], __float2int_rn(row_f * FSCALE));
        atomicAdd(&g_accum[batch][J * TILE + tid], __float2int_rn(s * FSCALE));

        __syncthreads();                       // REDs issued before arrival
        if (tid == 0)
            s_old[0] = arrive_acqrel(&g_arrive[batch][I]);
        if (tid == 32)
            s_old[1] = arrive_acqrel(&g_arrive[batch][J]);
    }
    __syncthreads();

    // Election: the 16th arriver finalizes that tile (1 load per output).
    const float b0 = bco[0];
    if (s_old[0] == NTILE - 1) {
        finalize_tile(batch, I, b0, out, tid);
        if (tid == 0) g_arrive[batch][I] = 0;   // reset for replay
    }
    if (s_old[1] == NTILE - 1) {
        finalize_tile(batch, J, b0, out, tid);
        if (tid == 32) g_arrive[batch][J] = 0;
    }
}

extern "C" void kernel_launch(void* const* d_in, const int* in_sizes, int n_in,
                              void* d_out, int out_size)
{
    const float* x = (const float*)d_in[0];
    const float* a = (const float*)d_in[1];
    const float* b = (const float*)d_in[2];
    float* out = (float*)d_out;

    dim3 grid(NPAIR, NBATCH);               // 136 x 16 = 2176 blocks
    sym_tile_kernel<<<grid, BT>>>(x, a, b, out);
}